// round 2
// baseline (speedup 1.0000x reference)
#include <cuda_runtime.h>

#define NN   65536
#define EE   524288
#define DIN  128
#define HD   256
#define NB   8
#define MROW 2048   // NB * HD

// ---------------- static device scratch (no allocations allowed) ----------------
__device__ float d_h0[NN * DIN];
__device__ float d_agg[NN * HD];
__device__ float d_hA[NN * HD];
__device__ float d_hB[NN * HD];
__device__ float d_cnt[NN];
__device__ float d_invcnt[NN];
__device__ float d_m1[MROW * HD];
__device__ float d_y[MROW];
__device__ float d_ybn[NB * HD];
__device__ float d_z[NB * HD];

// ---------------- utility kernels ----------------
__global__ void zero_kernel(float* __restrict__ p, int n) {
    int i = blockIdx.x * blockDim.x + threadIdx.x;
    if (i < n) p[i] = 0.0f;
}

__global__ void concat_kernel(const float* __restrict__ x,
                              const float* __restrict__ g0,
                              const float* __restrict__ g1,
                              const float* __restrict__ g2) {
    int i = blockIdx.x * blockDim.x + threadIdx.x;
    if (i >= NN * DIN) return;
    int n = i >> 7;
    int j = i & 127;
    float v;
    if (j < 32)       v = x[n * 32 + j];
    else if (j < 64)  v = g0[n * 32 + (j - 32)];
    else if (j < 96)  v = g1[n * 32 + (j - 64)];
    else              v = g2[n * 32 + (j - 96)];
    d_h0[i] = v;
}

__global__ void count_kernel(const int* __restrict__ dst) {
    int e = blockIdx.x * blockDim.x + threadIdx.x;
    if (e < EE) atomicAdd(&d_cnt[dst[e]], 1.0f);
}

__global__ void invcnt_kernel() {
    int n = blockIdx.x * blockDim.x + threadIdx.x;
    if (n < NN) d_invcnt[n] = 1.0f / fmaxf(d_cnt[n], 1.0f);
}

// one warp per edge: gather src row, scatter-add to dst row
__global__ void agg_kernel(const float* __restrict__ H,
                           const int* __restrict__ src,
                           const int* __restrict__ dst,
                           float* __restrict__ AGG, int dim) {
    int e = (blockIdx.x * blockDim.x + threadIdx.x) >> 5;
    int lane = threadIdx.x & 31;
    if (e >= EE) return;
    int s = __ldg(&src[e]);
    int d = __ldg(&dst[e]);
    const float4* Hs = reinterpret_cast<const float4*>(H + (size_t)s * dim);
    float* Ad = AGG + (size_t)d * dim;
    int dim4 = dim >> 2;
    for (int c = lane; c < dim4; c += 32) {
        float4 v = Hs[c];
        atomicAdd(Ad + c * 4 + 0, v.x);
        atomicAdd(Ad + c * 4 + 1, v.y);
        atomicAdd(Ad + c * 4 + 2, v.z);
        atomicAdd(Ad + c * 4 + 3, v.w);
    }
}

// ---------------- fused SAGE layer GEMM ----------------
// C[n, 0..255] = relu( (AGG[n,:]*invcnt[n]) @ Wl + H[n,:] @ Wr + bias )
// 128x128 output tile, BK=8, 256 threads, 8x8 per thread.
template <int K>
__global__ __launch_bounds__(256)
void sage_gemm(const float* __restrict__ A, const float* __restrict__ Hm,
               const float* __restrict__ Wl, const float* __restrict__ Wr,
               const float* __restrict__ bias, const float* __restrict__ invcnt,
               float* __restrict__ C) {
    __shared__ __align__(16) float As[8][128];
    __shared__ __align__(16) float Ws[8][128];

    const int tid = threadIdx.x;
    const int bm = blockIdx.x * 128;
    const int bn = blockIdx.y * 128;
    const int tx = tid & 15, ty = tid >> 4;

    const int aRow = bm + (tid >> 1);
    const int aCol = (tid & 1) * 4;
    const int wK = tid >> 5;
    const int wJ = (tid & 31) * 4;

    float acc[8][8];
#pragma unroll
    for (int i = 0; i < 8; i++)
#pragma unroll
        for (int j = 0; j < 8; j++) acc[i][j] = 0.0f;

    const float ic = invcnt[aRow];

#pragma unroll
    for (int phase = 0; phase < 2; ++phase) {
        const float* Asrc = phase ? Hm : A;
        const float* Wsrc = phase ? Wr : Wl;
        const float scale = phase ? 1.0f : ic;
        for (int k0 = 0; k0 < K; k0 += 8) {
            float4 av = *reinterpret_cast<const float4*>(Asrc + aRow * K + k0 + aCol);
            float4 wv = *reinterpret_cast<const float4*>(Wsrc + (k0 + wK) * HD + bn + wJ);
            __syncthreads();
            As[aCol + 0][tid >> 1] = av.x * scale;
            As[aCol + 1][tid >> 1] = av.y * scale;
            As[aCol + 2][tid >> 1] = av.z * scale;
            As[aCol + 3][tid >> 1] = av.w * scale;
            *reinterpret_cast<float4*>(&Ws[wK][wJ]) = wv;
            __syncthreads();
#pragma unroll
            for (int k = 0; k < 8; k++) {
                float a[8], w[8];
#pragma unroll
                for (int i = 0; i < 8; i++) a[i] = As[k][ty * 8 + i];
#pragma unroll
                for (int j = 0; j < 8; j++) w[j] = Ws[k][tx * 8 + j];
#pragma unroll
                for (int i = 0; i < 8; i++)
#pragma unroll
                    for (int j = 0; j < 8; j++) acc[i][j] += a[i] * w[j];
            }
        }
    }

#pragma unroll
    for (int i = 0; i < 8; i++) {
        int row = bm + ty * 8 + i;
#pragma unroll
        for (int j = 0; j < 8; j++) {
            int col = bn + tx * 8 + j;
            C[row * HD + col] = fmaxf(acc[i][j] + bias[col], 0.0f);
        }
    }
}

// ---------------- mlp1 GEMM: [2048, 8192] @ [8192, 256], split-K -> atomic accum ----------------
__global__ __launch_bounds__(256)
void mlp1_gemm(const float* __restrict__ A, const float* __restrict__ W,
               float* __restrict__ C) {
    __shared__ __align__(16) float As[8][128];
    __shared__ __align__(16) float Ws[8][128];

    const int tid = threadIdx.x;
    const int bm = blockIdx.x * 128;
    const int bn = blockIdx.y * 128;
    const int kb = blockIdx.z * 1024;
    const int tx = tid & 15, ty = tid >> 4;

    const int aRow = bm + (tid >> 1);
    const int aCol = (tid & 1) * 4;
    const int wK = tid >> 5;
    const int wJ = (tid & 31) * 4;

    float acc[8][8];
#pragma unroll
    for (int i = 0; i < 8; i++)
#pragma unroll
        for (int j = 0; j < 8; j++) acc[i][j] = 0.0f;

    for (int k0 = kb; k0 < kb + 1024; k0 += 8) {
        float4 av = *reinterpret_cast<const float4*>(A + (size_t)aRow * 8192 + k0 + aCol);
        float4 wv = *reinterpret_cast<const float4*>(W + (size_t)(k0 + wK) * HD + bn + wJ);
        __syncthreads();
        As[aCol + 0][tid >> 1] = av.x;
        As[aCol + 1][tid >> 1] = av.y;
        As[aCol + 2][tid >> 1] = av.z;
        As[aCol + 3][tid >> 1] = av.w;
        *reinterpret_cast<float4*>(&Ws[wK][wJ]) = wv;
        __syncthreads();
#pragma unroll
        for (int k = 0; k < 8; k++) {
            float a[8], w[8];
#pragma unroll
            for (int i = 0; i < 8; i++) a[i] = As[k][ty * 8 + i];
#pragma unroll
            for (int j = 0; j < 8; j++) w[j] = Ws[k][tx * 8 + j];
#pragma unroll
            for (int i = 0; i < 8; i++)
#pragma unroll
                for (int j = 0; j < 8; j++) acc[i][j] += a[i] * w[j];
        }
    }

#pragma unroll
    for (int i = 0; i < 8; i++) {
        int row = bm + ty * 8 + i;
#pragma unroll
        for (int j = 0; j < 8; j++) {
            int col = bn + tx * 8 + j;
            atomicAdd(&C[row * HD + col], acc[i][j]);
        }
    }
}

// y[row] = sum_c relu(M1[row,c] + b1[c]) * W2[c]  + b2
__global__ void mlp1_finalize(const float* __restrict__ M1,
                              const float* __restrict__ b1,
                              const float* __restrict__ W2,
                              const float* __restrict__ b2,
                              float* __restrict__ y) {
    int row = (blockIdx.x * blockDim.x + threadIdx.x) >> 5;
    int lane = threadIdx.x & 31;
    if (row >= MROW) return;
    float s = 0.0f;
    for (int c = lane; c < HD; c += 32)
        s += fmaxf(M1[row * HD + c] + b1[c], 0.0f) * W2[c];
#pragma unroll
    for (int o = 16; o; o >>= 1) s += __shfl_xor_sync(0xffffffffu, s, o);
    if (lane == 0) y[row] = s + b2[0];
}

// batchnorm over B=8 rows (population var), then relu
__global__ void bn_kernel(const float* __restrict__ y,
                          const float* __restrict__ gamma,
                          const float* __restrict__ beta,
                          float* __restrict__ ybn) {
    int hh = threadIdx.x;  // 256 threads
    float v[NB];
    float m = 0.0f;
#pragma unroll
    for (int b = 0; b < NB; b++) { v[b] = y[b * HD + hh]; m += v[b]; }
    m *= (1.0f / NB);
    float var = 0.0f;
#pragma unroll
    for (int b = 0; b < NB; b++) { float d = v[b] - m; var += d * d; }
    var *= (1.0f / NB);
    float inv = rsqrtf(var + 1e-5f) * gamma[hh];
    float be = beta[hh];
#pragma unroll
    for (int b = 0; b < NB; b++)
        ybn[b * HD + hh] = fmaxf((v[b] - m) * inv + be, 0.0f);
}

__global__ void mlp2a(const float* __restrict__ ybn, const float* __restrict__ W1,
                      const float* __restrict__ b1, float* __restrict__ z) {
    int b = blockIdx.x;
    int j = threadIdx.x;
    __shared__ float row[HD];
    row[j] = ybn[b * HD + j];
    __syncthreads();
    float s = b1[j];
    for (int hh = 0; hh < HD; hh++) s += row[hh] * W1[hh * HD + j];
    z[b * HD + j] = fmaxf(s, 0.0f);
}

__global__ void mlp2b(const float* __restrict__ z, const float* __restrict__ W2,
                      const float* __restrict__ b2, float* __restrict__ out) {
    int t = threadIdx.x;
    if (t >= NB * 8) return;
    int b = t >> 3, o = t & 7;
    float s = b2[o];
    for (int j = 0; j < HD; j++) s += z[b * HD + j] * W2[j * 8 + o];
    out[t] = s;
}

// ---------------- host launch ----------------
extern "C" void kernel_launch(void* const* d_in, const int* in_sizes, int n_in,
                              void* d_out, int out_size) {
    const float* x    = (const float*)d_in[0];
    const float* g0   = (const float*)d_in[1];
    const float* g1   = (const float*)d_in[2];
    const float* g2   = (const float*)d_in[3];
    const int*   esrc = (const int*)d_in[4];
    const int*   edst = (const int*)d_in[5];
    const float* Wl0  = (const float*)d_in[6];
    const float* Wr0  = (const float*)d_in[7];
    const float* b0   = (const float*)d_in[8];
    const float* Wl1  = (const float*)d_in[9];
    const float* Wr1  = (const float*)d_in[10];
    const float* b1   = (const float*)d_in[11];
    const float* Wl2  = (const float*)d_in[12];
    const float* Wr2  = (const float*)d_in[13];
    const float* b2   = (const float*)d_in[14];
    const float* Wl3  = (const float*)d_in[15];
    const float* Wr3  = (const float*)d_in[16];
    const float* b3   = (const float*)d_in[17];
    const float* m1W1 = (const float*)d_in[18];
    const float* m1b1 = (const float*)d_in[19];
    const float* m1W2 = (const float*)d_in[20];
    const float* m1b2 = (const float*)d_in[21];
    const float* gam  = (const float*)d_in[22];
    const float* bet  = (const float*)d_in[23];
    const float* m2W1 = (const float*)d_in[24];
    const float* m2b1 = (const float*)d_in[25];
    const float* m2W2 = (const float*)d_in[26];
    const float* m2b2 = (const float*)d_in[27];

    float *h0, *agg, *hA, *hB, *cnt, *icnt, *m1, *y, *ybn, *z;
    cudaGetSymbolAddress((void**)&h0, d_h0);
    cudaGetSymbolAddress((void**)&agg, d_agg);
    cudaGetSymbolAddress((void**)&hA, d_hA);
    cudaGetSymbolAddress((void**)&hB, d_hB);
    cudaGetSymbolAddress((void**)&cnt, d_cnt);
    cudaGetSymbolAddress((void**)&icnt, d_invcnt);
    cudaGetSymbolAddress((void**)&m1, d_m1);
    cudaGetSymbolAddress((void**)&y, d_y);
    cudaGetSymbolAddress((void**)&ybn, d_ybn);
    cudaGetSymbolAddress((void**)&z, d_z);

    // input prep
    concat_kernel<<<(NN * DIN) / 256, 256>>>(x, g0, g1, g2);
    zero_kernel<<<NN / 256, 256>>>(cnt, NN);
    count_kernel<<<EE / 256, 256>>>(edst);
    invcnt_kernel<<<NN / 256, 256>>>();

    // layer 0: K = 128
    zero_kernel<<<(NN * DIN) / 256, 256>>>(agg, NN * DIN);
    agg_kernel<<<EE / 8, 256>>>(h0, esrc, edst, agg, DIN);
    sage_gemm<DIN><<<dim3(NN / 128, 2), 256>>>(agg, h0, Wl0, Wr0, b0, icnt, hA);

    // layers 1..3: K = 256
    zero_kernel<<<(NN * HD) / 256, 256>>>(agg, NN * HD);
    agg_kernel<<<EE / 8, 256>>>(hA, esrc, edst, agg, HD);
    sage_gemm<HD><<<dim3(NN / 128, 2), 256>>>(agg, hA, Wl1, Wr1, b1, icnt, hB);

    zero_kernel<<<(NN * HD) / 256, 256>>>(agg, NN * HD);
    agg_kernel<<<EE / 8, 256>>>(hB, esrc, edst, agg, HD);
    sage_gemm<HD><<<dim3(NN / 128, 2), 256>>>(agg, hB, Wl2, Wr2, b2, icnt, hA);

    zero_kernel<<<(NN * HD) / 256, 256>>>(agg, NN * HD);
    agg_kernel<<<EE / 8, 256>>>(hA, esrc, edst, agg, HD);
    sage_gemm<HD><<<dim3(NN / 128, 2), 256>>>(agg, hA, Wl3, Wr3, b3, icnt, hB);

    // mlp1: flat hB as [2048, 8192] @ [8192, 256]
    zero_kernel<<<(MROW * HD) / 256, 256>>>(m1, MROW * HD);
    mlp1_gemm<<<dim3(MROW / 128, 2, 8), 256>>>(hB, m1W1, m1);
    mlp1_finalize<<<MROW / 8, 256>>>(m1, m1b1, m1W2, m1b2, y);

    // bn + mlp2 + output
    bn_kernel<<<1, 256>>>(y, gam, bet, ybn);
    mlp2a<<<NB, 256>>>(ybn, m2W1, m2b1, z);
    mlp2b<<<1, 64>>>(z, m2W2, m2b2, (float*)d_out);
}

// round 4
// speedup vs baseline: 2.0984x; 2.0984x over previous
#include <cuda_runtime.h>
#include <cuda_bf16.h>
#include <cstdint>

#define NN   65536
#define EE   524288
#define DIN  128
#define HD   256
#define NB   8
#define MROW 2048   // NB * HD

// ======================= helpers =======================
__device__ __forceinline__ void split_bf16(float v, __nv_bfloat16& h, __nv_bfloat16& l) {
    h = __float2bfloat16(v);
    l = __float2bfloat16(v - __bfloat162float(h));
}

// mma.sync m16n8k16 bf16 -> fp32 (baseline PTX, valid on sm_103 without 'a')
__device__ __forceinline__ void mma16816(float* c, const uint32_t* a, const uint32_t* b) {
    asm volatile(
        "mma.sync.aligned.m16n8k16.row.col.f32.bf16.bf16.f32 "
        "{%0,%1,%2,%3}, {%4,%5,%6,%7}, {%8,%9}, {%0,%1,%2,%3};"
        : "+f"(c[0]), "+f"(c[1]), "+f"(c[2]), "+f"(c[3])
        : "r"(a[0]), "r"(a[1]), "r"(a[2]), "r"(a[3]), "r"(b[0]), "r"(b[1]));
}

// ======================= static device scratch =======================
__device__ __nv_bfloat16 d_h02[NN * 256];               // concat, hi|lo (K=128)
__device__ __nv_bfloat16 d_agg2[NN * 512];              // agg, hi|lo
__device__ __nv_bfloat16 d_h2A[NN * 512];               // layer acts, hi|lo (K=256)
__device__ __nv_bfloat16 d_h2B[NN * 512];
__device__ __nv_bfloat16 d_m1A2[(size_t)MROW * 16384];  // layer3 out in mlp1 layout
__device__ __nv_bfloat16 d_w2[8][256 * 512];            // per-layer Wl/Wr transposed hi|lo
__device__ __nv_bfloat16 d_m1w2[(size_t)256 * 16384];   // mlp1 W1 transposed hi|lo
__device__ int   d_cnt[NN];
__device__ int   d_off[NN + 1];
__device__ int   d_cur[NN];
__device__ int   d_csr[EE];
__device__ float d_invcnt[NN];
__device__ float d_m1[MROW * HD];
__device__ float d_y[MROW];
__device__ float d_ybn[NB * HD];
__device__ float d_z[NB * HD];

// ======================= small kernels =======================
__global__ void zero_f(float* __restrict__ p, int n) {
    int i = blockIdx.x * blockDim.x + threadIdx.x;
    if (i < n) p[i] = 0.0f;
}
__global__ void zero_i(int* __restrict__ p, int n) {
    int i = blockIdx.x * blockDim.x + threadIdx.x;
    if (i < n) p[i] = 0;
}

__global__ void concat2_kernel(const float* __restrict__ x, const float* __restrict__ g0,
                               const float* __restrict__ g1, const float* __restrict__ g2) {
    int i = blockIdx.x * blockDim.x + threadIdx.x;
    if (i >= NN * 128) return;
    int n = i >> 7, j = i & 127;
    float v;
    if (j < 32)       v = x[n * 32 + j];
    else if (j < 64)  v = g0[n * 32 + (j - 32)];
    else if (j < 96)  v = g1[n * 32 + (j - 64)];
    else              v = g2[n * 32 + (j - 96)];
    __nv_bfloat16 h, l; split_bf16(v, h, l);
    d_h02[n * 256 + j]       = h;
    d_h02[n * 256 + 128 + j] = l;
}

// W [K,256] fp32 -> out [256][2K] bf16: row n = [hi(k=0..K-1) | lo]
__global__ void conv_w(const float* __restrict__ W, __nv_bfloat16* __restrict__ out, int K) {
    int i = blockIdx.x * blockDim.x + threadIdx.x;
    if (i >= K * 256) return;
    int n = i & 255, k = i >> 8;
    float v = W[k * 256 + n];
    __nv_bfloat16 h, l; split_bf16(v, h, l);
    out[(size_t)n * 2 * K + k]     = h;
    out[(size_t)n * 2 * K + K + k] = l;
}

__global__ void count_kernel(const int* __restrict__ dst) {
    int e = blockIdx.x * blockDim.x + threadIdx.x;
    if (e < EE) atomicAdd(&d_cnt[dst[e]], 1);
}

__global__ void invcnt_kernel() {
    int n = blockIdx.x * blockDim.x + threadIdx.x;
    if (n < NN) d_invcnt[n] = 1.0f / fmaxf((float)d_cnt[n], 1.0f);
}

// exclusive scan of d_cnt -> d_off (single block, 1024 threads, 64 each)
__global__ void scan_kernel() {
    __shared__ int s[1024];
    int t = threadIdx.x;
    int base = t * 64;
    int sum = 0;
    for (int i = 0; i < 64; i++) sum += d_cnt[base + i];
    s[t] = sum;
    __syncthreads();
    for (int o = 1; o < 1024; o <<= 1) {
        int v = (t >= o) ? s[t - o] : 0;
        __syncthreads();
        s[t] += v;
        __syncthreads();
    }
    int run = s[t] - sum;  // exclusive prefix
    for (int i = 0; i < 64; i++) { d_off[base + i] = run; run += d_cnt[base + i]; }
    if (t == 1023) d_off[NN] = run;
}

__global__ void fill_kernel(const int* __restrict__ src, const int* __restrict__ dst) {
    int e = blockIdx.x * blockDim.x + threadIdx.x;
    if (e >= EE) return;
    int d = dst[e];
    int p = atomicAdd(&d_cur[d], 1);
    d_csr[d_off[d] + p] = src[e];
}

// CSR mean-aggregation: warp per node. Input/output rows are [hi(D) | lo(D)] bf16.
template <int D>
__global__ void agg_csr(const __nv_bfloat16* __restrict__ H2,
                        __nv_bfloat16* __restrict__ out2) {
    int w = (blockIdx.x * blockDim.x + threadIdx.x) >> 5;
    int lane = threadIdx.x & 31;
    if (w >= NN) return;
    int s0 = __ldg(&d_off[w]), s1 = __ldg(&d_off[w + 1]);
    constexpr int R = D / 64;
    float a0[R], a1[R];
#pragma unroll
    for (int r = 0; r < R; r++) { a0[r] = 0.0f; a1[r] = 0.0f; }
    for (int p = s0; p < s1; p++) {
        int nb = __ldg(&d_csr[p]);
        const __nv_bfloat16* base = H2 + (size_t)nb * (2 * D);
#pragma unroll
        for (int r = 0; r < R; r++) {
            int c2 = (lane + r * 32) * 2;
            __nv_bfloat162 hv = *reinterpret_cast<const __nv_bfloat162*>(base + c2);
            __nv_bfloat162 lv = *reinterpret_cast<const __nv_bfloat162*>(base + D + c2);
            float2 hf = __bfloat1622float2(hv);
            float2 lf = __bfloat1622float2(lv);
            a0[r] += hf.x + lf.x;
            a1[r] += hf.y + lf.y;
        }
    }
    float ic = d_invcnt[w];
    __nv_bfloat16* ob = out2 + (size_t)w * (2 * D);
#pragma unroll
    for (int r = 0; r < R; r++) {
        float v0 = a0[r] * ic, v1 = a1[r] * ic;
        __nv_bfloat16 h0, l0, h1, l1;
        split_bf16(v0, h0, l0);
        split_bf16(v1, h1, l1);
        int c2 = (lane + r * 32) * 2;
        *reinterpret_cast<__nv_bfloat162*>(ob + c2)     = __nv_bfloat162{h0, h1};
        *reinterpret_cast<__nv_bfloat162*>(ob + D + c2) = __nv_bfloat162{l0, l1};
    }
}

// ======================= mma.sync SAGE layer GEMM =======================
// C[128 x 128-tile of 256] = relu( agg@Wl + h@Wr + b ), bf16 hi/lo 3-term split.
// A rows [hi(K)|lo(K)] stride 2K; W transposed [256][2K] (n-major, k-contiguous).
// Block 256 thr = 8 warps (4 m x 2 n); warp tile 32x64; smem rows padded to 72.
#define SPAD 72

template <int K>
__global__ __launch_bounds__(256)
void sage_mma(const __nv_bfloat16* __restrict__ agg2, const __nv_bfloat16* __restrict__ h2,
              const __nv_bfloat16* __restrict__ Wl2, const __nv_bfloat16* __restrict__ Wr2,
              const float* __restrict__ bias, __nv_bfloat16* __restrict__ out2, int mode) {
    __shared__ __align__(16) __nv_bfloat16 As[128][SPAD];
    __shared__ __align__(16) __nv_bfloat16 Bs[128][SPAD];

    const int tid = threadIdx.x;
    const int wid = tid >> 5, lane = tid & 31;
    const int wm = wid & 3, wn = wid >> 2;        // 4 x 2 warps
    const int lr = lane >> 2, lq = lane & 3;
    const int bm = blockIdx.x * 128;
    const int bn = blockIdx.y * 128;
    constexpr int K2 = 2 * K;

    const int ldr = tid >> 3;        // 0..31 (row group for tile loads)
    const int ldc = (tid & 7) * 8;   // bf16 col

    float acc[2][8][4];
#pragma unroll
    for (int i = 0; i < 2; i++)
#pragma unroll
        for (int j = 0; j < 8; j++)
#pragma unroll
            for (int t = 0; t < 4; t++) acc[i][j][t] = 0.0f;

    const __nv_bfloat16* Aseg[6] = {agg2, agg2 + K, agg2, h2, h2 + K, h2};
    const __nv_bfloat16* Bseg[6] = {Wl2, Wl2, Wl2 + K, Wr2, Wr2, Wr2 + K};

#pragma unroll
    for (int seg = 0; seg < 6; seg++) {
        const __nv_bfloat16* Ab = Aseg[seg] + (size_t)bm * K2;
        const __nv_bfloat16* Bb = Bseg[seg] + (size_t)bn * K2;
        for (int k0 = 0; k0 < K; k0 += 64) {
            __syncthreads();
#pragma unroll
            for (int j = 0; j < 4; j++) {
                int r = ldr + j * 32;
                uint4 va = *reinterpret_cast<const uint4*>(Ab + (size_t)r * K2 + k0 + ldc);
                uint4 vb = *reinterpret_cast<const uint4*>(Bb + (size_t)r * K2 + k0 + ldc);
                *reinterpret_cast<uint4*>(&As[r][ldc]) = va;
                *reinterpret_cast<uint4*>(&Bs[r][ldc]) = vb;
            }
            __syncthreads();
#pragma unroll
            for (int kk = 0; kk < 64; kk += 16) {
                uint32_t af[2][4];
#pragma unroll
                for (int mt = 0; mt < 2; mt++) {
                    int row = wm * 32 + mt * 16 + lr;
                    af[mt][0] = *reinterpret_cast<const uint32_t*>(&As[row][kk + lq * 2]);
                    af[mt][1] = *reinterpret_cast<const uint32_t*>(&As[row + 8][kk + lq * 2]);
                    af[mt][2] = *reinterpret_cast<const uint32_t*>(&As[row][kk + 8 + lq * 2]);
                    af[mt][3] = *reinterpret_cast<const uint32_t*>(&As[row + 8][kk + 8 + lq * 2]);
                }
#pragma unroll
                for (int nt = 0; nt < 8; nt++) {
                    int nrow = wn * 64 + nt * 8 + lr;
                    uint32_t bf[2];
                    bf[0] = *reinterpret_cast<const uint32_t*>(&Bs[nrow][kk + lq * 2]);
                    bf[1] = *reinterpret_cast<const uint32_t*>(&Bs[nrow][kk + 8 + lq * 2]);
                    mma16816(acc[0][nt], af[0], bf);
                    mma16816(acc[1][nt], af[1], bf);
                }
            }
        }
    }

    // epilogue: bias + relu + hi/lo split, direct bf16 stores
#pragma unroll
    for (int mt = 0; mt < 2; mt++) {
#pragma unroll
        for (int nt = 0; nt < 8; nt++) {
            int col = bn + wn * 64 + nt * 8 + lq * 2;
            float bs0 = __ldg(&bias[col]), bs1 = __ldg(&bias[col + 1]);
#pragma unroll
            for (int half = 0; half < 2; half++) {
                int grow = bm + wm * 32 + mt * 16 + lr + half * 8;
                float v0 = fmaxf(acc[mt][nt][half * 2 + 0] + bs0, 0.0f);
                float v1 = fmaxf(acc[mt][nt][half * 2 + 1] + bs1, 0.0f);
                __nv_bfloat16 h0, l0, h1, l1;
                split_bf16(v0, h0, l0);
                split_bf16(v1, h1, l1);
                if (mode == 0) {
                    *reinterpret_cast<__nv_bfloat162*>(&out2[(size_t)grow * 512 + col]) =
                        __nv_bfloat162{h0, h1};
                    *reinterpret_cast<__nv_bfloat162*>(&out2[(size_t)grow * 512 + 256 + col]) =
                        __nv_bfloat162{l0, l1};
                } else {
                    int R = grow >> 5;
                    int m = ((grow & 31) << 8) + col;
                    *reinterpret_cast<__nv_bfloat162*>(&out2[(size_t)R * 16384 + m]) =
                        __nv_bfloat162{h0, h1};
                    *reinterpret_cast<__nv_bfloat162*>(&out2[(size_t)R * 16384 + 8192 + m]) =
                        __nv_bfloat162{l0, l1};
                }
            }
        }
    }
}

// ======================= mma.sync mlp1 GEMM (split-K=8, atomic accum) ============
// A2 [2048][16384] (hi|lo), W2t [256][16384] (hi|lo), C [2048][256] fp32 (raw sums).
__global__ __launch_bounds__(256)
void mlp1_mma(const __nv_bfloat16* __restrict__ A2, const __nv_bfloat16* __restrict__ W2t,
              float* __restrict__ C) {
    __shared__ __align__(16) __nv_bfloat16 As[128][SPAD];
    __shared__ __align__(16) __nv_bfloat16 Bs[128][SPAD];

    const int tid = threadIdx.x;
    const int wid = tid >> 5, lane = tid & 31;
    const int wm = wid & 3, wn = wid >> 2;
    const int lr = lane >> 2, lq = lane & 3;
    const int bm = blockIdx.x * 128;
    const int bn = blockIdx.y * 128;
    const int g0 = blockIdx.z * 48;   // 384 chunks / 8 z-slices

    const int ldr = tid >> 3;
    const int ldc = (tid & 7) * 8;

    float acc[2][8][4];
#pragma unroll
    for (int i = 0; i < 2; i++)
#pragma unroll
        for (int j = 0; j < 8; j++)
#pragma unroll
            for (int t = 0; t < 4; t++) acc[i][j][t] = 0.0f;

    for (int i = 0; i < 48; i++) {
        int g = g0 + i;
        int t = g >> 7;           // 0: hi*hi, 1: lo*hi, 2: hi*lo
        int c = g & 127;
        const __nv_bfloat16* Ab = A2 + (size_t)bm * 16384 + ((t == 1) ? 8192 : 0) + c * 64;
        const __nv_bfloat16* Bb = W2t + (size_t)bn * 16384 + ((t == 2) ? 8192 : 0) + c * 64;
        __syncthreads();
#pragma unroll
        for (int j = 0; j < 4; j++) {
            int r = ldr + j * 32;
            uint4 va = *reinterpret_cast<const uint4*>(Ab + (size_t)r * 16384 + ldc);
            uint4 vb = *reinterpret_cast<const uint4*>(Bb + (size_t)r * 16384 + ldc);
            *reinterpret_cast<uint4*>(&As[r][ldc]) = va;
            *reinterpret_cast<uint4*>(&Bs[r][ldc]) = vb;
        }
        __syncthreads();
#pragma unroll
        for (int kk = 0; kk < 64; kk += 16) {
            uint32_t af[2][4];
#pragma unroll
            for (int mt = 0; mt < 2; mt++) {
                int row = wm * 32 + mt * 16 + lr;
                af[mt][0] = *reinterpret_cast<const uint32_t*>(&As[row][kk + lq * 2]);
                af[mt][1] = *reinterpret_cast<const uint32_t*>(&As[row + 8][kk + lq * 2]);
                af[mt][2] = *reinterpret_cast<const uint32_t*>(&As[row][kk + 8 + lq * 2]);
                af[mt][3] = *reinterpret_cast<const uint32_t*>(&As[row + 8][kk + 8 + lq * 2]);
            }
#pragma unroll
            for (int nt = 0; nt < 8; nt++) {
                int nrow = wn * 64 + nt * 8 + lr;
                uint32_t bf[2];
                bf[0] = *reinterpret_cast<const uint32_t*>(&Bs[nrow][kk + lq * 2]);
                bf[1] = *reinterpret_cast<const uint32_t*>(&Bs[nrow][kk + 8 + lq * 2]);
                mma16816(acc[0][nt], af[0], bf);
                mma16816(acc[1][nt], af[1], bf);
            }
        }
    }

#pragma unroll
    for (int mt = 0; mt < 2; mt++) {
#pragma unroll
        for (int nt = 0; nt < 8; nt++) {
            int col = bn + wn * 64 + nt * 8 + lq * 2;
#pragma unroll
            for (int half = 0; half < 2; half++) {
                int row = bm + wm * 32 + mt * 16 + lr + half * 8;
                atomicAdd(&C[(size_t)row * 256 + col],     acc[mt][nt][half * 2 + 0]);
                atomicAdd(&C[(size_t)row * 256 + col + 1], acc[mt][nt][half * 2 + 1]);
            }
        }
    }
}

// ======================= tail kernels =======================
__global__ void mlp1_finalize(const float* __restrict__ M1, const float* __restrict__ b1,
                              const float* __restrict__ W2, const float* __restrict__ b2,
                              float* __restrict__ y) {
    int row = (blockIdx.x * blockDim.x + threadIdx.x) >> 5;
    int lane = threadIdx.x & 31;
    if (row >= MROW) return;
    float s = 0.0f;
    for (int c = lane; c < HD; c += 32)
        s += fmaxf(M1[row * HD + c] + b1[c], 0.0f) * W2[c];
#pragma unroll
    for (int o = 16; o; o >>= 1) s += __shfl_xor_sync(0xffffffffu, s, o);
    if (lane == 0) y[row] = s + b2[0];
}

__global__ void bn_kernel(const float* __restrict__ y, const float* __restrict__ gamma,
                          const float* __restrict__ beta, float* __restrict__ ybn) {
    int hh = threadIdx.x;
    float v[NB];
    float m = 0.0f;
#pragma unroll
    for (int b = 0; b < NB; b++) { v[b] = y[b * HD + hh]; m += v[b]; }
    m *= (1.0f / NB);
    float var = 0.0f;
#pragma unroll
    for (int b = 0; b < NB; b++) { float d = v[b] - m; var += d * d; }
    var *= (1.0f / NB);
    float inv = rsqrtf(var + 1e-5f) * gamma[hh];
    float be = beta[hh];
#pragma unroll
    for (int b = 0; b < NB; b++)
        ybn[b * HD + hh] = fmaxf((v[b] - m) * inv + be, 0.0f);
}

__global__ void mlp2a(const float* __restrict__ ybn, const float* __restrict__ W1,
                      const float* __restrict__ b1, float* __restrict__ z) {
    int b = blockIdx.x;
    int j = threadIdx.x;
    __shared__ float row[HD];
    row[j] = ybn[b * HD + j];
    __syncthreads();
    float s = b1[j];
    for (int hh = 0; hh < HD; hh++) s += row[hh] * W1[hh * HD + j];
    z[b * HD + j] = fmaxf(s, 0.0f);
}

__global__ void mlp2b(const float* __restrict__ z, const float* __restrict__ W2,
                      const float* __restrict__ b2, float* __restrict__ out) {
    int t = threadIdx.x;
    if (t >= NB * 8) return;
    int b = t >> 3, o = t & 7;
    float s = b2[o];
    for (int j = 0; j < HD; j++) s += z[b * HD + j] * W2[j * 8 + o];
    out[t] = s;
}

// ======================= host launch =======================
extern "C" void kernel_launch(void* const* d_in, const int* in_sizes, int n_in,
                              void* d_out, int out_size) {
    const float* x    = (const float*)d_in[0];
    const float* g0   = (const float*)d_in[1];
    const float* g1   = (const float*)d_in[2];
    const float* g2   = (const float*)d_in[3];
    const int*   esrc = (const int*)d_in[4];
    const int*   edst = (const int*)d_in[5];
    const float* Wl0  = (const float*)d_in[6];
    const float* Wr0  = (const float*)d_in[7];
    const float* b0   = (const float*)d_in[8];
    const float* Wl1  = (const float*)d_in[9];
    const float* Wr1  = (const float*)d_in[10];
    const float* b1   = (const float*)d_in[11];
    const float* Wl2  = (const float*)d_in[12];
    const float* Wr2  = (const float*)d_in[13];
    const float* b2   = (const float*)d_in[14];
    const float* Wl3  = (const float*)d_in[15];
    const float* Wr3  = (const float*)d_in[16];
    const float* b3   = (const float*)d_in[17];
    const float* m1W1 = (const float*)d_in[18];
    const float* m1b1 = (const float*)d_in[19];
    const float* m1W2 = (const float*)d_in[20];
    const float* m1b2 = (const float*)d_in[21];
    const float* gam  = (const float*)d_in[22];
    const float* bet  = (const float*)d_in[23];
    const float* m2W1 = (const float*)d_in[24];
    const float* m2b1 = (const float*)d_in[25];
    const float* m2W2 = (const float*)d_in[26];
    const float* m2b2 = (const float*)d_in[27];

    __nv_bfloat16 *h02, *agg2, *h2A, *h2B, *m1A2, *w2, *m1w2;
    int *cnt, *cur;
    float *m1, *y, *ybn, *z;
    cudaGetSymbolAddress((void**)&h02, d_h02);
    cudaGetSymbolAddress((void**)&agg2, d_agg2);
    cudaGetSymbolAddress((void**)&h2A, d_h2A);
    cudaGetSymbolAddress((void**)&h2B, d_h2B);
    cudaGetSymbolAddress((void**)&m1A2, d_m1A2);
    cudaGetSymbolAddress((void**)&w2, d_w2);
    cudaGetSymbolAddress((void**)&m1w2, d_m1w2);
    cudaGetSymbolAddress((void**)&cnt, d_cnt);
    cudaGetSymbolAddress((void**)&cur, d_cur);
    cudaGetSymbolAddress((void**)&m1, d_m1);
    cudaGetSymbolAddress((void**)&y, d_y);
    cudaGetSymbolAddress((void**)&ybn, d_ybn);
    cudaGetSymbolAddress((void**)&z, d_z);

    __nv_bfloat16* wl[4] = {w2 + 0 * 256 * 512, w2 + 2 * 256 * 512, w2 + 4 * 256 * 512, w2 + 6 * 256 * 512};
    __nv_bfloat16* wr[4] = {w2 + 1 * 256 * 512, w2 + 3 * 256 * 512, w2 + 5 * 256 * 512, w2 + 7 * 256 * 512};

    // weight conversion (transposed, hi/lo split)
    conv_w<<<128, 256>>>(Wl0, wl[0], 128);
    conv_w<<<128, 256>>>(Wr0, wr[0], 128);
    conv_w<<<256, 256>>>(Wl1, wl[1], 256);
    conv_w<<<256, 256>>>(Wr1, wr[1], 256);
    conv_w<<<256, 256>>>(Wl2, wl[2], 256);
    conv_w<<<256, 256>>>(Wr2, wr[2], 256);
    conv_w<<<256, 256>>>(Wl3, wl[3], 256);
    conv_w<<<256, 256>>>(Wr3, wr[3], 256);
    conv_w<<<8192, 256>>>(m1W1, m1w2, 8192);

    // inputs + CSR build
    concat2_kernel<<<(NN * 128) / 256, 256>>>(x, g0, g1, g2);
    zero_i<<<NN / 256, 256>>>(cnt, NN);
    count_kernel<<<EE / 256, 256>>>(edst);
    invcnt_kernel<<<NN / 256, 256>>>();
    scan_kernel<<<1, 1024>>>();
    zero_i<<<NN / 256, 256>>>(cur, NN);
    fill_kernel<<<EE / 256, 256>>>(esrc, edst);

    // layer 0 (K=128)
    agg_csr<128><<<NN / 8, 256>>>(h02, agg2);
    sage_mma<128><<<dim3(NN / 128, 2), 256>>>(agg2, h02, wl[0], wr[0], b0, h2A, 0);
    // layer 1
    agg_csr<256><<<NN / 8, 256>>>(h2A, agg2);
    sage_mma<256><<<dim3(NN / 128, 2), 256>>>(agg2, h2A, wl[1], wr[1], b1, h2B, 0);
    // layer 2
    agg_csr<256><<<NN / 8, 256>>>(h2B, agg2);
    sage_mma<256><<<dim3(NN / 128, 2), 256>>>(agg2, h2B, wl[2], wr[2], b2, h2A, 0);
    // layer 3 -> mlp1 layout
    agg_csr<256><<<NN / 8, 256>>>(h2A, agg2);
    sage_mma<256><<<dim3(NN / 128, 2), 256>>>(agg2, h2A, wl[3], wr[3], b3, m1A2, 1);

    // mlp1
    zero_f<<<(MROW * HD) / 256, 256>>>(m1, MROW * HD);
    mlp1_mma<<<dim3(MROW / 128, 2, 8), 256>>>(m1A2, m1w2, m1);
    mlp1_finalize<<<MROW / 8, 256>>>(m1, m1b1, m1W2, m1b2, y);

    // tail
    bn_kernel<<<1, 256>>>(y, gam, bet, ybn);
    mlp2a<<<NB, 256>>>(ybn, m2W1, m2b1, z);
    mlp2b<<<1, 64>>>(z, m2W2, m2b2, (float*)d_out);
}

// round 5
// speedup vs baseline: 2.7433x; 1.3073x over previous
#include <cuda_runtime.h>
#include <cuda_bf16.h>
#include <cstdint>

#define NN   65536
#define EE   524288
#define DIN  128
#define HD   256
#define NB   8
#define MROW 2048   // NB * HD

// ======================= helpers =======================
__device__ __forceinline__ void split_bf16(float v, __nv_bfloat16& h, __nv_bfloat16& l) {
    h = __float2bfloat16(v);
    l = __float2bfloat16(v - __bfloat162float(h));
}

__device__ __forceinline__ void mma16816(float* c, const uint32_t* a, const uint32_t* b) {
    asm volatile(
        "mma.sync.aligned.m16n8k16.row.col.f32.bf16.bf16.f32 "
        "{%0,%1,%2,%3}, {%4,%5,%6,%7}, {%8,%9}, {%0,%1,%2,%3};"
        : "+f"(c[0]), "+f"(c[1]), "+f"(c[2]), "+f"(c[3])
        : "r"(a[0]), "r"(a[1]), "r"(a[2]), "r"(a[3]), "r"(b[0]), "r"(b[1]));
}

__device__ __forceinline__ uint32_t smem_u32(const void* p) {
    uint32_t a;
    asm("{ .reg .u64 t; cvta.to.shared.u64 t, %1; cvt.u32.u64 %0, t; }" : "=r"(a) : "l"(p));
    return a;
}

__device__ __forceinline__ void cpa16(uint32_t dst, const void* src) {
    asm volatile("cp.async.cg.shared.global [%0], [%1], 16;" :: "r"(dst), "l"(src));
}
#define CPA_COMMIT() asm volatile("cp.async.commit_group;" ::: "memory")
#define CPA_WAIT1()  asm volatile("cp.async.wait_group 1;" ::: "memory")
#define CPA_WAIT0()  asm volatile("cp.async.wait_group 0;" ::: "memory")

// smem tiling: 4 tiles (Ah, Al, Bh, Bl), each 128 rows x 40 bf16 (32 data + 8 pad)
#define TSTRIDE 40
#define TE (128 * TSTRIDE)          // elements per tile
#define BUFE (4 * TE)               // elements per buffer
#define GEMM_SMEM_BYTES (2 * BUFE * 2)  // 81920 B

// ======================= static device scratch =======================
__device__ __nv_bfloat16 d_h02[NN * 256];
__device__ __nv_bfloat16 d_agg2[NN * 512];
__device__ __nv_bfloat16 d_h2A[NN * 512];
__device__ __nv_bfloat16 d_h2B[NN * 512];
__device__ __nv_bfloat16 d_m1A2[(size_t)MROW * 16384];
__device__ __nv_bfloat16 d_w2[8][256 * 512];
__device__ __nv_bfloat16 d_m1w2[(size_t)256 * 16384];
__device__ int   d_cnt[NN];
__device__ int   d_off[NN + 1];
__device__ int   d_cur[NN];
__device__ int   d_csr[EE];
__device__ float d_invcnt[NN];
__device__ float d_m1[MROW * HD];
__device__ float d_y[MROW];
__device__ float d_ybn[NB * HD];
__device__ float d_z[NB * HD];

// ======================= small kernels =======================
__global__ void zero_f(float* __restrict__ p, int n) {
    int i = blockIdx.x * blockDim.x + threadIdx.x;
    if (i < n) p[i] = 0.0f;
}
__global__ void zero_i(int* __restrict__ p, int n) {
    int i = blockIdx.x * blockDim.x + threadIdx.x;
    if (i < n) p[i] = 0;
}

__global__ void concat2_kernel(const float* __restrict__ x, const float* __restrict__ g0,
                               const float* __restrict__ g1, const float* __restrict__ g2) {
    int i = blockIdx.x * blockDim.x + threadIdx.x;
    if (i >= NN * 128) return;
    int n = i >> 7, j = i & 127;
    float v;
    if (j < 32)       v = x[n * 32 + j];
    else if (j < 64)  v = g0[n * 32 + (j - 32)];
    else if (j < 96)  v = g1[n * 32 + (j - 64)];
    else              v = g2[n * 32 + (j - 96)];
    __nv_bfloat16 h, l; split_bf16(v, h, l);
    d_h02[n * 256 + j]       = h;
    d_h02[n * 256 + 128 + j] = l;
}

__global__ void conv_w(const float* __restrict__ W, __nv_bfloat16* __restrict__ out, int K) {
    int i = blockIdx.x * blockDim.x + threadIdx.x;
    if (i >= K * 256) return;
    int n = i & 255, k = i >> 8;
    float v = W[k * 256 + n];
    __nv_bfloat16 h, l; split_bf16(v, h, l);
    out[(size_t)n * 2 * K + k]     = h;
    out[(size_t)n * 2 * K + K + k] = l;
}

__global__ void count_kernel(const int* __restrict__ dst) {
    int e = blockIdx.x * blockDim.x + threadIdx.x;
    if (e < EE) atomicAdd(&d_cnt[dst[e]], 1);
}

__global__ void invcnt_kernel() {
    int n = blockIdx.x * blockDim.x + threadIdx.x;
    if (n < NN) d_invcnt[n] = 1.0f / fmaxf((float)d_cnt[n], 1.0f);
}

__global__ void scan_kernel() {
    __shared__ int s[1024];
    int t = threadIdx.x;
    int base = t * 64;
    int sum = 0;
    for (int i = 0; i < 64; i++) sum += d_cnt[base + i];
    s[t] = sum;
    __syncthreads();
    for (int o = 1; o < 1024; o <<= 1) {
        int v = (t >= o) ? s[t - o] : 0;
        __syncthreads();
        s[t] += v;
        __syncthreads();
    }
    int run = s[t] - sum;
    for (int i = 0; i < 64; i++) { d_off[base + i] = run; run += d_cnt[base + i]; }
    if (t == 1023) d_off[NN] = run;
}

__global__ void fill_kernel(const int* __restrict__ src, const int* __restrict__ dst) {
    int e = blockIdx.x * blockDim.x + threadIdx.x;
    if (e >= EE) return;
    int d = dst[e];
    int p = atomicAdd(&d_cur[d], 1);
    d_csr[d_off[d] + p] = src[e];
}

// CSR mean-aggregation: warp per node. Rows are [hi(D) | lo(D)] bf16.
template <int D>
__global__ void agg_csr(const __nv_bfloat16* __restrict__ H2,
                        __nv_bfloat16* __restrict__ out2) {
    int w = (blockIdx.x * blockDim.x + threadIdx.x) >> 5;
    int lane = threadIdx.x & 31;
    if (w >= NN) return;
    int s0 = __ldg(&d_off[w]), s1 = __ldg(&d_off[w + 1]);
    constexpr int R = D / 64;
    float a0[R], a1[R];
#pragma unroll
    for (int r = 0; r < R; r++) { a0[r] = 0.0f; a1[r] = 0.0f; }
    for (int p = s0; p < s1; p++) {
        int nb = __ldg(&d_csr[p]);
        const __nv_bfloat16* base = H2 + (size_t)nb * (2 * D);
#pragma unroll
        for (int r = 0; r < R; r++) {
            int c2 = (lane + r * 32) * 2;
            __nv_bfloat162 hv = *reinterpret_cast<const __nv_bfloat162*>(base + c2);
            __nv_bfloat162 lv = *reinterpret_cast<const __nv_bfloat162*>(base + D + c2);
            float2 hf = __bfloat1622float2(hv);
            float2 lf = __bfloat1622float2(lv);
            a0[r] += hf.x + lf.x;
            a1[r] += hf.y + lf.y;
        }
    }
    float ic = d_invcnt[w];
    __nv_bfloat16* ob = out2 + (size_t)w * (2 * D);
#pragma unroll
    for (int r = 0; r < R; r++) {
        float v0 = a0[r] * ic, v1 = a1[r] * ic;
        __nv_bfloat16 h0, l0, h1, l1;
        split_bf16(v0, h0, l0);
        split_bf16(v1, h1, l1);
        int c2 = (lane + r * 32) * 2;
        *reinterpret_cast<__nv_bfloat162*>(ob + c2)     = __nv_bfloat162{h0, h1};
        *reinterpret_cast<__nv_bfloat162*>(ob + D + c2) = __nv_bfloat162{l0, l1};
    }
}

// ======================= GEMM compute core (shared by both kernels) =======================
// Computes 3-term split MMAs (AhBh + AlBh + AhBl) from resident chunk tiles.
__device__ __forceinline__ void gemm_chunk(const __nv_bfloat16* Sm, int wm, int wn,
                                           int lr, int lq, float acc[2][8][4]) {
    const __nv_bfloat16* Ah = Sm;
    const __nv_bfloat16* Al = Sm + TE;
    const __nv_bfloat16* Bh = Sm + 2 * TE;
    const __nv_bfloat16* Bl = Sm + 3 * TE;
#pragma unroll
    for (int kk = 0; kk < 32; kk += 16) {
        uint32_t afh[2][4], afl[2][4];
#pragma unroll
        for (int mt = 0; mt < 2; mt++) {
            int row = wm * 32 + mt * 16 + lr;
            afh[mt][0] = *reinterpret_cast<const uint32_t*>(&Ah[row * TSTRIDE + kk + lq * 2]);
            afh[mt][1] = *reinterpret_cast<const uint32_t*>(&Ah[(row + 8) * TSTRIDE + kk + lq * 2]);
            afh[mt][2] = *reinterpret_cast<const uint32_t*>(&Ah[row * TSTRIDE + kk + 8 + lq * 2]);
            afh[mt][3] = *reinterpret_cast<const uint32_t*>(&Ah[(row + 8) * TSTRIDE + kk + 8 + lq * 2]);
            afl[mt][0] = *reinterpret_cast<const uint32_t*>(&Al[row * TSTRIDE + kk + lq * 2]);
            afl[mt][1] = *reinterpret_cast<const uint32_t*>(&Al[(row + 8) * TSTRIDE + kk + lq * 2]);
            afl[mt][2] = *reinterpret_cast<const uint32_t*>(&Al[row * TSTRIDE + kk + 8 + lq * 2]);
            afl[mt][3] = *reinterpret_cast<const uint32_t*>(&Al[(row + 8) * TSTRIDE + kk + 8 + lq * 2]);
        }
#pragma unroll
        for (int nt = 0; nt < 8; nt++) {
            int nrow = wn * 64 + nt * 8 + lr;
            uint32_t bfh[2], bfl[2];
            bfh[0] = *reinterpret_cast<const uint32_t*>(&Bh[nrow * TSTRIDE + kk + lq * 2]);
            bfh[1] = *reinterpret_cast<const uint32_t*>(&Bh[nrow * TSTRIDE + kk + 8 + lq * 2]);
            mma16816(acc[0][nt], afh[0], bfh);
            mma16816(acc[1][nt], afh[1], bfh);
            mma16816(acc[0][nt], afl[0], bfh);
            mma16816(acc[1][nt], afl[1], bfh);
            bfl[0] = *reinterpret_cast<const uint32_t*>(&Bl[nrow * TSTRIDE + kk + lq * 2]);
            bfl[1] = *reinterpret_cast<const uint32_t*>(&Bl[nrow * TSTRIDE + kk + 8 + lq * 2]);
            mma16816(acc[0][nt], afh[0], bfl);
            mma16816(acc[1][nt], afh[1], bfl);
        }
    }
}

// ======================= SAGE layer GEMM (cp.async double-buffered) ===============
template <int K>
__global__ __launch_bounds__(256, 2)
void sage_mma(const __nv_bfloat16* __restrict__ agg2, const __nv_bfloat16* __restrict__ h2,
              const __nv_bfloat16* __restrict__ Wl2, const __nv_bfloat16* __restrict__ Wr2,
              const float* __restrict__ bias, __nv_bfloat16* __restrict__ out2, int mode) {
    extern __shared__ __nv_bfloat16 smdyn[];
    const uint32_t smbase = smem_u32(smdyn);

    const int tid = threadIdx.x;
    const int wid = tid >> 5, lane = tid & 31;
    const int wm = wid & 3, wn = wid >> 2;
    const int lr = lane >> 2, lq = lane & 3;
    const int bm = blockIdx.x * 128;
    const int bn = blockIdx.y * 128;
    constexpr int K2 = 2 * K;
    constexpr int CPS = K / 32;       // chunks per source
    constexpr int NCH = 2 * CPS;

    const int r0 = tid >> 2;          // 0..63
    const int cb = (tid & 3) * 8;     // bf16 col offset within 32-col chunk

    float acc[2][8][4];
#pragma unroll
    for (int i = 0; i < 2; i++)
#pragma unroll
        for (int j = 0; j < 8; j++)
#pragma unroll
            for (int t = 0; t < 4; t++) acc[i][j][t] = 0.0f;

    auto prefetch = [&](int ci, int b) {
        const __nv_bfloat16* Asrc = (ci < CPS) ? agg2 : h2;
        const __nv_bfloat16* Bsrc = (ci < CPS) ? Wl2 : Wr2;
        int c = ci & (CPS - 1);
        uint32_t sb = smbase + (uint32_t)b * (BUFE * 2);
#pragma unroll
        for (int half = 0; half < 2; half++) {
            int r = r0 + half * 64;
            uint32_t so = (uint32_t)(r * TSTRIDE + cb) * 2;
            const __nv_bfloat16* Ap = Asrc + (size_t)(bm + r) * K2 + c * 32 + cb;
            const __nv_bfloat16* Bp = Bsrc + (size_t)(bn + r) * K2 + c * 32 + cb;
            cpa16(sb + 0 * TE * 2 + so, Ap);
            cpa16(sb + 1 * TE * 2 + so, Ap + K);
            cpa16(sb + 2 * TE * 2 + so, Bp);
            cpa16(sb + 3 * TE * 2 + so, Bp + K);
        }
        CPA_COMMIT();
    };

    prefetch(0, 0);
    for (int i = 0; i < NCH; i++) {
        int b = i & 1;
        if (i + 1 < NCH) { prefetch(i + 1, b ^ 1); CPA_WAIT1(); }
        else             { CPA_WAIT0(); }
        __syncthreads();
        gemm_chunk(smdyn + b * BUFE, wm, wn, lr, lq, acc);
        __syncthreads();
    }

    // epilogue: bias + relu + hi/lo split
#pragma unroll
    for (int mt = 0; mt < 2; mt++) {
#pragma unroll
        for (int nt = 0; nt < 8; nt++) {
            int col = bn + wn * 64 + nt * 8 + lq * 2;
            float bs0 = __ldg(&bias[col]), bs1 = __ldg(&bias[col + 1]);
#pragma unroll
            for (int half = 0; half < 2; half++) {
                int grow = bm + wm * 32 + mt * 16 + lr + half * 8;
                float v0 = fmaxf(acc[mt][nt][half * 2 + 0] + bs0, 0.0f);
                float v1 = fmaxf(acc[mt][nt][half * 2 + 1] + bs1, 0.0f);
                __nv_bfloat16 h0, l0, h1, l1;
                split_bf16(v0, h0, l0);
                split_bf16(v1, h1, l1);
                if (mode == 0) {
                    *reinterpret_cast<__nv_bfloat162*>(&out2[(size_t)grow * 512 + col]) =
                        __nv_bfloat162{h0, h1};
                    *reinterpret_cast<__nv_bfloat162*>(&out2[(size_t)grow * 512 + 256 + col]) =
                        __nv_bfloat162{l0, l1};
                } else {
                    int R = grow >> 5;
                    int m = ((grow & 31) << 8) + col;
                    *reinterpret_cast<__nv_bfloat162*>(&out2[(size_t)R * 16384 + m]) =
                        __nv_bfloat162{h0, h1};
                    *reinterpret_cast<__nv_bfloat162*>(&out2[(size_t)R * 16384 + 8192 + m]) =
                        __nv_bfloat162{l0, l1};
                }
            }
        }
    }
}

// ======================= mlp1 GEMM (split-K=8, cp.async, atomic accum) ============
__global__ __launch_bounds__(256, 2)
void mlp1_mma(const __nv_bfloat16* __restrict__ A2, const __nv_bfloat16* __restrict__ W2t,
              float* __restrict__ C) {
    extern __shared__ __nv_bfloat16 smdyn[];
    const uint32_t smbase = smem_u32(smdyn);

    const int tid = threadIdx.x;
    const int wid = tid >> 5, lane = tid & 31;
    const int wm = wid & 3, wn = wid >> 2;
    const int lr = lane >> 2, lq = lane & 3;
    const int bm = blockIdx.x * 128;
    const int bn = blockIdx.y * 128;
    const int g0 = blockIdx.z * 32;   // 256 chunks / 8 z-slices
    const int NCH = 32;

    const int r0 = tid >> 2;
    const int cb = (tid & 3) * 8;

    float acc[2][8][4];
#pragma unroll
    for (int i = 0; i < 2; i++)
#pragma unroll
        for (int j = 0; j < 8; j++)
#pragma unroll
            for (int t = 0; t < 4; t++) acc[i][j][t] = 0.0f;

    auto prefetch = [&](int i, int b) {
        int c = g0 + i;
        uint32_t sb = smbase + (uint32_t)b * (BUFE * 2);
#pragma unroll
        for (int half = 0; half < 2; half++) {
            int r = r0 + half * 64;
            uint32_t so = (uint32_t)(r * TSTRIDE + cb) * 2;
            const __nv_bfloat16* Ap = A2 + (size_t)(bm + r) * 16384 + c * 32 + cb;
            const __nv_bfloat16* Bp = W2t + (size_t)(bn + r) * 16384 + c * 32 + cb;
            cpa16(sb + 0 * TE * 2 + so, Ap);
            cpa16(sb + 1 * TE * 2 + so, Ap + 8192);
            cpa16(sb + 2 * TE * 2 + so, Bp);
            cpa16(sb + 3 * TE * 2 + so, Bp + 8192);
        }
        CPA_COMMIT();
    };

    prefetch(0, 0);
    for (int i = 0; i < NCH; i++) {
        int b = i & 1;
        if (i + 1 < NCH) { prefetch(i + 1, b ^ 1); CPA_WAIT1(); }
        else             { CPA_WAIT0(); }
        __syncthreads();
        gemm_chunk(smdyn + b * BUFE, wm, wn, lr, lq, acc);
        __syncthreads();
    }

#pragma unroll
    for (int mt = 0; mt < 2; mt++) {
#pragma unroll
        for (int nt = 0; nt < 8; nt++) {
            int col = bn + wn * 64 + nt * 8 + lq * 2;
#pragma unroll
            for (int half = 0; half < 2; half++) {
                int row = bm + wm * 32 + mt * 16 + lr + half * 8;
                atomicAdd(&C[(size_t)row * 256 + col],     acc[mt][nt][half * 2 + 0]);
                atomicAdd(&C[(size_t)row * 256 + col + 1], acc[mt][nt][half * 2 + 1]);
            }
        }
    }
}

// ======================= tail kernels =======================
__global__ void mlp1_finalize(const float* __restrict__ M1, const float* __restrict__ b1,
                              const float* __restrict__ W2, const float* __restrict__ b2,
                              float* __restrict__ y) {
    int row = (blockIdx.x * blockDim.x + threadIdx.x) >> 5;
    int lane = threadIdx.x & 31;
    if (row >= MROW) return;
    float s = 0.0f;
    for (int c = lane; c < HD; c += 32)
        s += fmaxf(M1[row * HD + c] + b1[c], 0.0f) * W2[c];
#pragma unroll
    for (int o = 16; o; o >>= 1) s += __shfl_xor_sync(0xffffffffu, s, o);
    if (lane == 0) y[row] = s + b2[0];
}

__global__ void bn_kernel(const float* __restrict__ y, const float* __restrict__ gamma,
                          const float* __restrict__ beta, float* __restrict__ ybn) {
    int hh = threadIdx.x;
    float v[NB];
    float m = 0.0f;
#pragma unroll
    for (int b = 0; b < NB; b++) { v[b] = y[b * HD + hh]; m += v[b]; }
    m *= (1.0f / NB);
    float var = 0.0f;
#pragma unroll
    for (int b = 0; b < NB; b++) { float d = v[b] - m; var += d * d; }
    var *= (1.0f / NB);
    float inv = rsqrtf(var + 1e-5f) * gamma[hh];
    float be = beta[hh];
#pragma unroll
    for (int b = 0; b < NB; b++)
        ybn[b * HD + hh] = fmaxf((v[b] - m) * inv + be, 0.0f);
}

__global__ void mlp2a(const float* __restrict__ ybn, const float* __restrict__ W1,
                      const float* __restrict__ b1, float* __restrict__ z) {
    int b = blockIdx.x;
    int j = threadIdx.x;
    __shared__ float row[HD];
    row[j] = ybn[b * HD + j];
    __syncthreads();
    float s = b1[j];
    for (int hh = 0; hh < HD; hh++) s += row[hh] * W1[hh * HD + j];
    z[b * HD + j] = fmaxf(s, 0.0f);
}

__global__ void mlp2b(const float* __restrict__ z, const float* __restrict__ W2,
                      const float* __restrict__ b2, float* __restrict__ out) {
    int t = threadIdx.x;
    if (t >= NB * 8) return;
    int b = t >> 3, o = t & 7;
    float s = b2[o];
    for (int j = 0; j < HD; j++) s += z[b * HD + j] * W2[j * 8 + o];
    out[t] = s;
}

// ======================= host launch =======================
extern "C" void kernel_launch(void* const* d_in, const int* in_sizes, int n_in,
                              void* d_out, int out_size) {
    const float* x    = (const float*)d_in[0];
    const float* g0   = (const float*)d_in[1];
    const float* g1   = (const float*)d_in[2];
    const float* g2   = (const float*)d_in[3];
    const int*   esrc = (const int*)d_in[4];
    const int*   edst = (const int*)d_in[5];
    const float* Wl0  = (const float*)d_in[6];
    const float* Wr0  = (const float*)d_in[7];
    const float* b0   = (const float*)d_in[8];
    const float* Wl1  = (const float*)d_in[9];
    const float* Wr1  = (const float*)d_in[10];
    const float* b1   = (const float*)d_in[11];
    const float* Wl2  = (const float*)d_in[12];
    const float* Wr2  = (const float*)d_in[13];
    const float* b2   = (const float*)d_in[14];
    const float* Wl3  = (const float*)d_in[15];
    const float* Wr3  = (const float*)d_in[16];
    const float* b3   = (const float*)d_in[17];
    const float* m1W1 = (const float*)d_in[18];
    const float* m1b1 = (const float*)d_in[19];
    const float* m1W2 = (const float*)d_in[20];
    const float* m1b2 = (const float*)d_in[21];
    const float* gam  = (const float*)d_in[22];
    const float* bet  = (const float*)d_in[23];
    const float* m2W1 = (const float*)d_in[24];
    const float* m2b1 = (const float*)d_in[25];
    const float* m2W2 = (const float*)d_in[26];
    const float* m2b2 = (const float*)d_in[27];

    __nv_bfloat16 *h02, *agg2, *h2A, *h2B, *m1A2, *w2, *m1w2;
    int *cnt, *cur;
    float *m1, *y, *ybn, *z;
    cudaGetSymbolAddress((void**)&h02, d_h02);
    cudaGetSymbolAddress((void**)&agg2, d_agg2);
    cudaGetSymbolAddress((void**)&h2A, d_h2A);
    cudaGetSymbolAddress((void**)&h2B, d_h2B);
    cudaGetSymbolAddress((void**)&m1A2, d_m1A2);
    cudaGetSymbolAddress((void**)&w2, d_w2);
    cudaGetSymbolAddress((void**)&m1w2, d_m1w2);
    cudaGetSymbolAddress((void**)&cnt, d_cnt);
    cudaGetSymbolAddress((void**)&cur, d_cur);
    cudaGetSymbolAddress((void**)&m1, d_m1);
    cudaGetSymbolAddress((void**)&y, d_y);
    cudaGetSymbolAddress((void**)&ybn, d_ybn);
    cudaGetSymbolAddress((void**)&z, d_z);

    cudaFuncSetAttribute(sage_mma<128>, cudaFuncAttributeMaxDynamicSharedMemorySize, GEMM_SMEM_BYTES);
    cudaFuncSetAttribute(sage_mma<256>, cudaFuncAttributeMaxDynamicSharedMemorySize, GEMM_SMEM_BYTES);
    cudaFuncSetAttribute(mlp1_mma,      cudaFuncAttributeMaxDynamicSharedMemorySize, GEMM_SMEM_BYTES);

    __nv_bfloat16* wl[4] = {w2 + 0 * 256 * 512, w2 + 2 * 256 * 512, w2 + 4 * 256 * 512, w2 + 6 * 256 * 512};
    __nv_bfloat16* wr[4] = {w2 + 1 * 256 * 512, w2 + 3 * 256 * 512, w2 + 5 * 256 * 512, w2 + 7 * 256 * 512};

    conv_w<<<128, 256>>>(Wl0, wl[0], 128);
    conv_w<<<128, 256>>>(Wr0, wr[0], 128);
    conv_w<<<256, 256>>>(Wl1, wl[1], 256);
    conv_w<<<256, 256>>>(Wr1, wr[1], 256);
    conv_w<<<256, 256>>>(Wl2, wl[2], 256);
    conv_w<<<256, 256>>>(Wr2, wr[2], 256);
    conv_w<<<256, 256>>>(Wl3, wl[3], 256);
    conv_w<<<256, 256>>>(Wr3, wr[3], 256);
    conv_w<<<8192, 256>>>(m1W1, m1w2, 8192);

    concat2_kernel<<<(NN * 128) / 256, 256>>>(x, g0, g1, g2);
    zero_i<<<NN / 256, 256>>>(cnt, NN);
    count_kernel<<<EE / 256, 256>>>(edst);
    invcnt_kernel<<<NN / 256, 256>>>();
    scan_kernel<<<1, 1024>>>();
    zero_i<<<NN / 256, 256>>>(cur, NN);
    fill_kernel<<<EE / 256, 256>>>(esrc, edst);

    agg_csr<128><<<NN / 8, 256>>>(h02, agg2);
    sage_mma<128><<<dim3(NN / 128, 2), 256, GEMM_SMEM_BYTES>>>(agg2, h02, wl[0], wr[0], b0, h2A, 0);
    agg_csr<256><<<NN / 8, 256>>>(h2A, agg2);
    sage_mma<256><<<dim3(NN / 128, 2), 256, GEMM_SMEM_BYTES>>>(agg2, h2A, wl[1], wr[1], b1, h2B, 0);
    agg_csr<256><<<NN / 8, 256>>>(h2B, agg2);
    sage_mma<256><<<dim3(NN / 128, 2), 256, GEMM_SMEM_BYTES>>>(agg2, h2B, wl[2], wr[2], b2, h2A, 0);
    agg_csr<256><<<NN / 8, 256>>>(h2A, agg2);
    sage_mma<256><<<dim3(NN / 128, 2), 256, GEMM_SMEM_BYTES>>>(agg2, h2A, wl[3], wr[3], b3, m1A2, 1);

    zero_f<<<(MROW * HD) / 256, 256>>>(m1, MROW * HD);
    mlp1_mma<<<dim3(MROW / 128, 2, 8), 256, GEMM_SMEM_BYTES>>>(m1A2, m1w2, m1);
    mlp1_finalize<<<MROW / 8, 256>>>(m1, m1b1, m1W2, m1b2, y);

    bn_kernel<<<1, 256>>>(y, gam, bet, ybn);
    mlp2a<<<NB, 256>>>(ybn, m2W1, m2b1, z);
    mlp2b<<<1, 64>>>(z, m2W2, m2b2, (float*)d_out);
}